// round 1
// baseline (speedup 1.0000x reference)
#include <cuda_runtime.h>
#include <cuda_bf16.h>
#include <cstddef>

// WKV2D: B=8, H=16, W=16, C=256 (fixed by setup_inputs).
//
// k_adj[b,c,y,x] = sum_{i,j} relu(k[b,c,i,j] - w[c]*(|i-y|+|j-x|))  (+u bonus at center)
// out = exp(k_adj) * v
//
// Key facts exploited:
//  * zero-padding taps contribute exactly 0 (k=0, d>=1, w>0)
//  * terms with d >= floor(kmax_c / w_c) + 2 are exactly 0
//    -> only a small Manhattan diamond of radius r = floor(kmax/w)+1 matters.

#define B_DIM 8
#define HW 256          // 16*16 pixels
#define C_DIM 256
#define CCH 8           // channels per block
#define KS_STRIDE 9     // [px][c] padded stride -> conflict-free LDS

__global__ __launch_bounds__(256, 4)
void wkv2d_kernel(const float* __restrict__ w,
                  const float* __restrict__ u,
                  const float* __restrict__ k,
                  const float* __restrict__ v,
                  float* __restrict__ out)
{
    __shared__ float ks[HW * KS_STRIDE];     // k tile, [px][c], stride 9
    __shared__ float red[32 * KS_STRIDE];    // partial maxes [g][c]
    __shared__ float s_wneg[CCH];
    __shared__ float s_u[CCH];
    __shared__ int   s_r[CCH];

    const int b  = blockIdx.x >> 5;          // 32 channel-chunks per batch
    const int c0 = (blockIdx.x & 31) * CCH;
    const int t  = threadIdx.x;
    const int c  = t & 7;                    // channel within chunk
    const int g  = t >> 3;                   // 0..31

    const size_t base = ((size_t)b * HW) * C_DIM + c0;
    const float* kb = k + base;

    // ---- stage k tile into shared (coalesced: 8 consecutive ch per pixel) ----
    #pragma unroll
    for (int m = 0; m < 8; m++) {
        int px = g + 32 * m;
        ks[px * KS_STRIDE + c] = kb[(size_t)px * C_DIM + c];
    }
    if (t < CCH) {
        float wv = w[c0 + t];
        s_wneg[t] = -wv;
        s_u[t]    = u[c0 + t];
    }
    __syncthreads();

    // ---- per-channel max (2-level reduction) ----
    float m8 = -1e30f;
    #pragma unroll
    for (int j = 0; j < 8; j++)
        m8 = fmaxf(m8, ks[(g * 8 + j) * KS_STRIDE + c]);
    red[g * KS_STRIDE + c] = m8;
    __syncthreads();

    if (t < CCH) {
        float mm = -1e30f;
        #pragma unroll 8
        for (int gg = 0; gg < 32; gg++)
            mm = fmaxf(mm, red[gg * KS_STRIDE + t]);
        float wv = -s_wneg[t];
        // safe radius: all terms with d > r are exactly zero
        // (w*(r+1) >= kmax + w, margin >> fp rounding of w*d)
        int r = (int)(fmaxf(mm, 0.0f) / wv) + 1;
        s_r[t] = min(r, 30);
    }
    __syncthreads();

    // block-uniform radius (extra channels' terms are provably zero)
    int r = 0;
    #pragma unroll
    for (int cc = 0; cc < CCH; cc++) r = max(r, s_r[cc]);

    const float wneg = s_wneg[c];
    const float uu   = s_u[c];
    const float* vb  = v + base;
    float*       ob  = out + base;

    #pragma unroll
    for (int j = 0; j < 8; j++) {
        int px = g * 8 + j;
        int y = px >> 4, x = px & 15;

        float acc = 0.0f;
        for (int di = -r; di <= r; di++) {
            int iy = y + di;
            if ((unsigned)iy >= 16u) continue;
            int adi = di < 0 ? -di : di;
            int rr  = r - adi;
            int rowb = iy * 16;
            float fdi = (float)adi;
            for (int dj = -rr; dj <= rr; dj++) {
                int ix = x + dj;
                if ((unsigned)ix >= 16u) continue;
                int adj_ = dj < 0 ? -dj : dj;
                float d = fdi + (float)adj_;
                float val = fmaf(wneg, d, ks[(rowb + ix) * KS_STRIDE + c]);
                acc += fmaxf(0.0f, val);
            }
        }
        // center bonus: replace relu(kc) with relu(kc + u)
        float kc = ks[px * KS_STRIDE + c];
        acc += fmaxf(0.0f, kc + uu) - fmaxf(0.0f, kc);

        ob[(size_t)px * C_DIM + c] = __expf(acc) * vb[(size_t)px * C_DIM + c];
    }
}

extern "C" void kernel_launch(void* const* d_in, const int* in_sizes, int n_in,
                              void* d_out, int out_size)
{
    // Identify tensors by element count (robust to scalar B/H/W/C placement):
    // size 256     -> w, then u
    // size 524288  -> k, then v
    const float *w = nullptr, *u = nullptr, *k = nullptr, *v = nullptr;
    for (int i = 0; i < n_in; i++) {
        if (in_sizes[i] == C_DIM) {
            if (!w) w = (const float*)d_in[i];
            else if (!u) u = (const float*)d_in[i];
        } else if (in_sizes[i] == B_DIM * HW * C_DIM) {
            if (!k) k = (const float*)d_in[i];
            else if (!v) v = (const float*)d_in[i];
        }
    }
    wkv2d_kernel<<<B_DIM * (C_DIM / CCH), 256>>>(w, u, k, v, (float*)d_out);
}

// round 2
// speedup vs baseline: 2.3513x; 2.3513x over previous
#include <cuda_runtime.h>
#include <cuda_bf16.h>
#include <cstddef>

// WKV2D: B=8, H=16, W=16, C=256.
// k_adj[b,c,y,x] = sum_{taps} relu(k - w[c]*manhattan_dist) (+u bonus at center)
// out = exp(k_adj) * v
//
// Sparsity: taps with d >= floor(kmax_c/w_c)+2 are exactly zero -> small diamond.
// Halo trick: shared tile padded with -1e30 => relu(halo - w*d) == 0, no bounds checks.

#define B_DIM   8
#define HW      256
#define C_DIM   256
#define CCH     4           // channels per block
#define PAD     4           // halo radius (fast path covers r <= 4)
#define TW      24          // padded tile width  (16 + 2*PAD)
#define CSTRIDE 584         // 24*24=576 padded to 584 (== 8 mod 32 -> conflict-free)

// Fully-unrolled diamond accumulation over 4 pixels (ILP-4), compile-time radius.
template<int R>
__device__ __forceinline__ void diamond(const float* __restrict__ ksb, int pos0,
                                        float wneg, float acc[4])
{
    #pragma unroll
    for (int di = -R; di <= R; ++di) {
        const int adi = di < 0 ? -di : di;
        const int rr  = R - adi;
        #pragma unroll
        for (int dj = -rr; dj <= rr; ++dj) {
            const int adj = dj < 0 ? -dj : dj;
            const float wd = wneg * (float)(adi + adj);   // CSE'd per distance
            const int off = pos0 + di * TW + dj;
            #pragma unroll
            for (int j = 0; j < 4; ++j)
                acc[j] += fmaxf(0.0f, ksb[off + 96 * j] + wd);
        }
    }
}

__global__ __launch_bounds__(256, 4)
void wkv2d_kernel(const float* __restrict__ w,
                  const float* __restrict__ u,
                  const float* __restrict__ k,
                  const float* __restrict__ v,
                  float* __restrict__ out)
{
    __shared__ float ks[CCH * CSTRIDE];      // padded tiles, [c][pos]
    __shared__ float red[8 * CCH];           // per-warp per-channel maxes
    __shared__ float s_wneg[CCH];
    __shared__ float s_u[CCH];
    __shared__ int   s_r[CCH];

    const int b  = blockIdx.x >> 6;          // 64 chunks of 4 channels per batch
    const int c0 = (blockIdx.x & 63) * CCH;
    const int t  = threadIdx.x;

    const size_t base = ((size_t)b * HW) * C_DIM + c0;
    const float* kb = k + base;

    // ---- fill padded tile with -1e30 (halo => exact zeros in relu) ----
    #pragma unroll
    for (int i = t; i < CCH * CSTRIDE; i += 256)
        ks[i] = -1e30f;
    if (t < CCH) {
        s_wneg[t] = -w[c0 + t];
        s_u[t]    = u[c0 + t];
    }
    __syncthreads();

    // ---- load interior: 4ch x 256px = 1024 floats, 4 per thread ----
    #pragma unroll
    for (int j = 0; j < 4; ++j) {
        int idx = t + 256 * j;               // (px, cc) = (idx>>2, idx&3)
        int px  = idx >> 2;
        int cc  = idx & 3;
        int y = px >> 4, x = px & 15;
        ks[cc * CSTRIDE + (y + PAD) * TW + (x + PAD)] = kb[(size_t)px * C_DIM + cc];
    }
    __syncthreads();

    // ---- compute mapping: c = t&3, pixels q + 64j ----
    const int c = t & 3;
    const int q = t >> 2;                    // 0..63
    const int y0 = q >> 4, x0 = q & 15;
    const int pos0 = (y0 + PAD) * TW + (x0 + PAD);
    const float* ksb = ks + c * CSTRIDE;

    // ---- per-channel max via shuffle (lanes with same c: xor 4,8,16) ----
    float m = -1e30f;
    #pragma unroll
    for (int j = 0; j < 4; ++j)
        m = fmaxf(m, ksb[pos0 + 96 * j]);
    #pragma unroll
    for (int s = 4; s <= 16; s <<= 1)
        m = fmaxf(m, __shfl_xor_sync(0xffffffffu, m, s));
    if ((t & 31) < CCH)
        red[(t >> 5) * CCH + c] = m;
    __syncthreads();

    if (t < CCH) {
        float mm = -1e30f;
        #pragma unroll
        for (int ww = 0; ww < 8; ++ww)
            mm = fmaxf(mm, red[ww * CCH + t]);
        float wv = -s_wneg[t];
        int r = (int)(fmaxf(mm, 0.0f) / wv) + 1;   // all taps with d > r are exactly 0
        s_r[t] = min(r, 30);
    }
    __syncthreads();

    int r = 0;
    #pragma unroll
    for (int cc = 0; cc < CCH; ++cc) r = max(r, s_r[cc]);

    const float wneg = s_wneg[c];
    const float uu   = s_u[c];

    float acc[4] = {0.f, 0.f, 0.f, 0.f};

    if (r <= 4) {
        switch (r) {
            case 1: diamond<1>(ksb, pos0, wneg, acc); break;
            case 2: diamond<2>(ksb, pos0, wneg, acc); break;
            case 3: diamond<3>(ksb, pos0, wneg, acc); break;
            default: diamond<4>(ksb, pos0, wneg, acc); break;
        }
    } else {
        // generic fallback (bounds-checked against the 16x16 interior)
        #pragma unroll
        for (int j = 0; j < 4; ++j) {
            int y = y0 + 4 * j, x = x0;
            float a = 0.f;
            for (int di = -r; di <= r; ++di) {
                int iy = y + di;
                if ((unsigned)iy >= 16u) continue;
                int adi = di < 0 ? -di : di;
                int rr = r - adi;
                for (int dj = -rr; dj <= rr; ++dj) {
                    int ix = x + dj;
                    if ((unsigned)ix >= 16u) continue;
                    int adj_ = dj < 0 ? -dj : dj;
                    float d = (float)(adi + adj_);
                    a += fmaxf(0.f, fmaf(wneg, d, ksb[(iy + PAD) * TW + ix + PAD]));
                }
            }
            acc[j] = a;
        }
    }

    // center bonus + epilogue
    const float* vb = v + base;
    float*       ob = out + base;
    #pragma unroll
    for (int j = 0; j < 4; ++j) {
        int px = q + 64 * j;
        float kc = ksb[pos0 + 96 * j];
        float a = acc[j] + fmaxf(0.f, kc + uu) - fmaxf(0.f, kc);
        ob[(size_t)px * C_DIM + c] = __expf(a) * vb[(size_t)px * C_DIM + c];
    }
}

extern "C" void kernel_launch(void* const* d_in, const int* in_sizes, int n_in,
                              void* d_out, int out_size)
{
    const float *w = nullptr, *u = nullptr, *k = nullptr, *v = nullptr;
    for (int i = 0; i < n_in; i++) {
        if (in_sizes[i] == C_DIM) {
            if (!w) w = (const float*)d_in[i];
            else if (!u) u = (const float*)d_in[i];
        } else if (in_sizes[i] == B_DIM * HW * C_DIM) {
            if (!k) k = (const float*)d_in[i];
            else if (!v) v = (const float*)d_in[i];
        }
    }
    wkv2d_kernel<<<B_DIM * (C_DIM / CCH), 256>>>(w, u, k, v, (float*)d_out);
}